// round 14
// baseline (speedup 1.0000x reference)
#include <cuda_runtime.h>
#include <cuda_fp16.h>
#include <cstdint>

#define NROWS 16384
#define DIN   512
#define DOUT  256

#define KC2 64
#define KT2 (NROWS / KC2)          // 256
#define A2SZ (128 * 128)           // 16 KB  (fp16 SW128)
#define B2SZ (256 * 128)           // 32 KB
#define STG2 (A2SZ + B2SZ)         // 48 KB
#define SMEM2 (1024 + 4 * STG2)

// scratch (packed SW128 tile layout: [kt][256 n-rows x 64 halfs])
__device__ uint4 g_Wp4[DIN * DOUT / 8];    // W packed: 8 tiles
__device__ uint4 g_Hp4[NROWS * DOUT / 8];  // H packed: 256 tiles
__device__ int   g_flags[KT2];             // H tile ready flags

// ---------------- helpers ----------------
__device__ __forceinline__ uint32_t smem_u32(const void* p) {
    uint32_t a;
    asm("{ .reg .u64 t; cvta.to.shared.u64 t, %1; cvt.u32.u64 %0, t; }"
        : "=r"(a) : "l"(p));
    return a;
}
__device__ __forceinline__ void sts64(uint32_t a, uint32_t x, uint32_t y) {
    asm volatile("st.shared.v2.b32 [%0], {%1, %2};" :: "r"(a), "r"(x), "r"(y) : "memory");
}
__device__ __forceinline__ uint32_t pack2(float x, float y) {
    __half2 h = __floats2half2_rn(x, y);
    return *reinterpret_cast<uint32_t*>(&h);
}
__device__ __forceinline__ void ldsm4(uint32_t* r, uint32_t addr) {
    asm volatile("ldmatrix.sync.aligned.m8n8.x4.shared.b16 {%0,%1,%2,%3}, [%4];"
                 : "=r"(r[0]), "=r"(r[1]), "=r"(r[2]), "=r"(r[3]) : "r"(addr));
}
__device__ __forceinline__ void mma16816(float* d, const uint32_t* a,
                                         uint32_t b0, uint32_t b1) {
    asm volatile(
        "mma.sync.aligned.m16n8k16.row.col.f32.f16.f16.f32 "
        "{%0,%1,%2,%3}, {%4,%5,%6,%7}, {%8,%9}, {%0,%1,%2,%3};"
        : "+f"(d[0]), "+f"(d[1]), "+f"(d[2]), "+f"(d[3])
        : "r"(a[0]), "r"(a[1]), "r"(a[2]), "r"(a[3]), "r"(b0), "r"(b1));
}
__device__ __forceinline__ void mbar_init(uint32_t addr, uint32_t count) {
    asm volatile("mbarrier.init.shared.b64 [%0], %1;" :: "r"(addr), "r"(count) : "memory");
}
__device__ __forceinline__ void mbar_expect_tx(uint32_t addr, uint32_t bytes) {
    asm volatile("mbarrier.arrive.expect_tx.shared.b64 _, [%0], %1;"
                 :: "r"(addr), "r"(bytes) : "memory");
}
__device__ __forceinline__ void mbar_arrive(uint32_t addr) {
    asm volatile("mbarrier.arrive.release.cta.shared.b64 _, [%0];" :: "r"(addr) : "memory");
}
__device__ __forceinline__ void mbar_wait(uint32_t addr, uint32_t parity) {
    asm volatile(
        "{\n\t.reg .pred P;\n\t"
        "W%=:\n\t"
        "mbarrier.try_wait.parity.acquire.cta.shared::cta.b64 P, [%0], %1, 0x989680;\n\t"
        "@!P bra W%=;\n\t"
        "}" :: "r"(addr), "r"(parity) : "memory");
}
__device__ __forceinline__ void bulk_g2s(uint32_t dst, const void* src,
                                         uint32_t bytes, uint32_t mbar) {
    asm volatile(
        "cp.async.bulk.shared::cta.global.mbarrier::complete_tx::bytes [%0], [%1], %2, [%3];"
        :: "r"(dst), "l"(src), "r"(bytes), "r"(mbar) : "memory");
}
__device__ __forceinline__ void flag_publish(int* f) {
    asm volatile("st.global.release.gpu.b32 [%0], %1;" :: "l"(f), "r"(1) : "memory");
}
__device__ __forceinline__ void flag_spin(const int* f) {
    int v;
    do {
        asm volatile("ld.global.acquire.gpu.b32 %0, [%1];" : "=r"(v) : "l"(f) : "memory");
        if (v) break;
        __nanosleep(64);
    } while (true);
}

// ---------------- W packing (+ flag reset) ----------------
__global__ void pack_w_kernel(const float* __restrict__ W) {
    int idx = blockIdx.x * blockDim.x + threadIdx.x;
    if (idx < KT2) g_flags[idx] = 0;
    if (idx >= DIN * DOUT) return;
    int k = idx / DOUT, n = idx % DOUT;
    int kt = k >> 6, kk = k & 63;
    int ch = kk >> 3, w = kk & 7;
    reinterpret_cast<__half*>(g_Wp4)[kt * 16384 + n * 64 + ((ch ^ (n & 7)) << 3) + w] =
        __float2half_rn(W[idx]);
}

// ---------------- merged GEMM kernel ----------------
// blocks 0..127   : gemm2 role — Out[tile] = A_hat @ H (spin-waits H tile flags)
// blocks 128..255 : gemm1 role — H[2 tiles] = X @ W + b (publishes flags)
__global__ void __launch_bounds__(384, 1)
gcn_merged(const float* __restrict__ X,
           const float* __restrict__ Ahat,
           float* __restrict__ out,
           const float* __restrict__ bias)
{
    const bool is_g2 = (blockIdx.x < 128);
    const int bid = is_g2 ? blockIdx.x : (blockIdx.x - 128);
    const float* Asrc = is_g2 ? Ahat : X;
    const long long lda = is_g2 ? NROWS : DIN;
    const int KT = is_g2 ? KT2 : (DIN / KC2);   // 256 or 8
    const uint4* Bp = is_g2 ? g_Hp4 : g_Wp4;

    extern __shared__ char sm[];
    const uint32_t sb = smem_u32(sm);
    const uint32_t mb = sb;
    const uint32_t tiles = sb + 1024;
    const int tid = threadIdx.x, lane = tid & 31, wid = tid >> 5;

    if (tid == 0) {
        #pragma unroll
        for (int s = 0; s < 4; s++) {
            mbar_init(mb + 8 * s, 129);      // full: 128 convert lanes + 1 tx-arrive
            mbar_init(mb + 32 + 8 * s, 8);   // empty
        }
    }
    __syncthreads();

    if (wid >= 8) {
        // ---- convert-producer warps (A-operand: fp32 gmem -> fp16 SW128 smem) ----
        const int w = wid - 8;
        const int lane4 = lane & 15, rh = lane >> 4;
        const int r0 = w * 32 + rh;
        const float* src0 = Asrc + (size_t)(bid * 128 + r0) * (size_t)lda + lane4 * 4;
        const uint32_t j16 = (uint32_t)(lane4 >> 1);
        const uint32_t low8 = (uint32_t)((lane4 & 1) * 8);

        for (int kt = 0; kt < KT; kt++) {
            int s = kt & 3, wrap = kt >> 2;
            if (kt >= 4) mbar_wait(mb + 32 + 8 * s, (wrap - 1) & 1);
            uint32_t stg = tiles + s * STG2;
            if (wid == 8 && lane == 0) {
                if (is_g2) {
                    flag_spin(&g_flags[kt]);   // H tile ready?
                    // order the acquire (generic proxy) before the async-proxy bulk read
                    asm volatile("fence.proxy.async.global;" ::: "memory");
                }
                mbar_expect_tx(mb + 8 * s, B2SZ);
                bulk_g2s(stg + A2SZ, Bp + (size_t)kt * 2048, B2SZ, mb + 8 * s);
            }
            const float* srck = src0 + kt * KC2;
            #pragma unroll
            for (int it = 0; it < 16; it++) {
                int r = r0 + 2 * it;
                float4 v = *reinterpret_cast<const float4*>(srck + (size_t)(2 * it) * lda);
                uint32_t off = (uint32_t)(r * 128) + (((j16 ^ (uint32_t)(r & 7)) << 4) + low8);
                sts64(stg + off, pack2(v.x, v.y), pack2(v.z, v.w));
            }
            mbar_arrive(mb + 8 * s);   // per-lane release arrive
        }
        if (!is_g2) {
            // participate in epilogue barriers + copy-out (bar 1 = 384 threads)
            asm volatile("bar.sync 1, 384;" ::: "memory");
            asm volatile("bar.sync 1, 384;" ::: "memory");
            const uint4* sm4 = reinterpret_cast<const uint4*>(sm + 1024);
            uint4* gdst = g_Hp4 + (size_t)bid * 4096;
            #pragma unroll
            for (int i = 0; i < 11; i++) {                 // 11*384 >= 4096
                int q = tid + i * 384;
                if (q < 4096) gdst[q] = sm4[q];
            }
            asm volatile("bar.sync 1, 384;" ::: "memory");
            __threadfence();
            // make generic-proxy H stores visible to consumers' async-proxy bulk reads
            asm volatile("fence.proxy.async.global;" ::: "memory");
            if (tid == 8 * 32) {
                flag_publish(&g_flags[2 * bid]);
                flag_publish(&g_flags[2 * bid + 1]);
            }
        }
        return;
    }

    // ---- compute warps (0..7), warp tile 64x64 ----
    const int warp_m = wid & 1, warp_n = wid >> 1;
    const int g = lane >> 2, c = lane & 3;

    float acc[4][8][4];
    #pragma unroll
    for (int mt = 0; mt < 4; mt++)
        #pragma unroll
        for (int nt = 0; nt < 8; nt++)
            #pragma unroll
            for (int e = 0; e < 4; e++) acc[mt][nt][e] = 0.f;

    const int arow = lane & 15, ahi = lane >> 4, s7 = lane & 7;
    const int brow = ((lane >> 4) << 3) + (lane & 7), bhi = (lane >> 3) & 1;
    uint32_t a_row_off[4], b_row_off[4];
    #pragma unroll
    for (int mt = 0; mt < 4; mt++)
        a_row_off[mt] = (uint32_t)((warp_m * 64 + mt * 16 + arow) * 128);
    #pragma unroll
    for (int ntp = 0; ntp < 4; ntp++)
        b_row_off[ntp] = (uint32_t)(A2SZ + (warp_n * 64 + ntp * 16 + brow) * 128);

    uint32_t afr[2][4][4], bfr[2][4][4];
    auto load_frags = [&](int buf, int k16, uint32_t stg) {
        uint32_t ja = (uint32_t)(((2 * k16 + ahi) ^ s7) << 4);
        #pragma unroll
        for (int mt = 0; mt < 4; mt++)
            ldsm4(afr[buf][mt], stg + a_row_off[mt] + ja);
        uint32_t jb = (uint32_t)(((2 * k16 + bhi) ^ s7) << 4);
        #pragma unroll
        for (int ntp = 0; ntp < 4; ntp++)
            ldsm4(bfr[buf][ntp], stg + b_row_off[ntp] + jb);
    };

    for (int kt = 0; kt < KT; kt++) {
        int s = kt & 3, ph = (kt >> 2) & 1;
        mbar_wait(mb + 8 * s, ph);
        uint32_t stg = tiles + s * STG2;
        load_frags(0, 0, stg);
        #pragma unroll
        for (int k16 = 0; k16 < 4; k16++) {
            int cur = k16 & 1;
            if (k16 < 3) load_frags(cur ^ 1, k16 + 1, stg);
            #pragma unroll
            for (int mt = 0; mt < 4; mt++)
                #pragma unroll
                for (int nt = 0; nt < 8; nt++)
                    mma16816(acc[mt][nt], afr[cur][mt],
                             bfr[cur][nt >> 1][(nt & 1) * 2],
                             bfr[cur][nt >> 1][(nt & 1) * 2 + 1]);
        }
        if (lane == 0) mbar_arrive(mb + 32 + 8 * s);   // stage consumed
    }

    if (is_g2) {
        int m0 = bid * 128 + warp_m * 64;
        #pragma unroll
        for (int mt = 0; mt < 4; mt++) {
            #pragma unroll
            for (int nt = 0; nt < 8; nt++) {
                int r = m0 + mt * 16 + g;
                int n = warp_n * 64 + nt * 8 + c * 2;
                *reinterpret_cast<float2*>(out + (size_t)r * DOUT + n) =
                    make_float2(acc[mt][nt][0], acc[mt][nt][1]);
                *reinterpret_cast<float2*>(out + (size_t)(r + 8) * DOUT + n) =
                    make_float2(acc[mt][nt][2], acc[mt][nt][3]);
            }
        }
    } else {
        // gemm1 epilogue: stage 2 packed H tiles in smem, coop copy-out
        asm volatile("bar.sync 1, 384;" ::: "memory");   // stages free (producers joined)
        __half* smh = reinterpret_cast<__half*>(sm + 1024);
        #pragma unroll
        for (int mt = 0; mt < 4; mt++) {
            int r = warp_m * 64 + mt * 16 + g;
            int t = r >> 6, kk = r & 63;
            int ch = kk >> 3, w = kk & 7;
            int tb = t * 16384;
            #pragma unroll
            for (int nt = 0; nt < 8; nt++) {
                int n = warp_n * 64 + nt * 8 + c * 2;
                float bn0 = bias[n], bn1 = bias[n + 1];
                int s0 = n & 7, s1 = (n + 1) & 7;
                smh[tb + n * 64       + ((ch ^ s0) << 3) + w] = __float2half_rn(acc[mt][nt][0] + bn0);
                smh[tb + (n + 1) * 64 + ((ch ^ s1) << 3) + w] = __float2half_rn(acc[mt][nt][1] + bn1);
                smh[tb + n * 64       + (((ch + 1) ^ s0) << 3) + w] = __float2half_rn(acc[mt][nt][2] + bn0);
                smh[tb + (n + 1) * 64 + (((ch + 1) ^ s1) << 3) + w] = __float2half_rn(acc[mt][nt][3] + bn1);
            }
        }
        asm volatile("bar.sync 1, 384;" ::: "memory");
        const uint4* sm4 = reinterpret_cast<const uint4*>(sm + 1024);
        uint4* gdst = g_Hp4 + (size_t)bid * 4096;
        #pragma unroll
        for (int i = 0; i < 11; i++) {                   // 11*384 >= 4096
            int q = tid + i * 384;
            if (q < 4096) gdst[q] = sm4[q];
        }
        asm volatile("bar.sync 1, 384;" ::: "memory");
        __threadfence();
        // flags published by producer-warp thread (tid 256) after this barrier
    }
}

// ---------------- launch ----------------
extern "C" void kernel_launch(void* const* d_in, const int* in_sizes, int n_in,
                              void* d_out, int out_size) {
    const float* X = (const float*)d_in[0];
    const float* A = (const float*)d_in[1];
    const float* W = (const float*)d_in[2];
    const float* b = (const float*)d_in[3];
    float* out = (float*)d_out;

    cudaFuncSetAttribute(gcn_merged, cudaFuncAttributeMaxDynamicSharedMemorySize, SMEM2);

    pack_w_kernel<<<(DIN * DOUT + 255) / 256, 256>>>(W);
    gcn_merged<<<256, 384, SMEM2>>>(X, A, out, b);
}

// round 15
// speedup vs baseline: 1.3561x; 1.3561x over previous
#include <cuda_runtime.h>
#include <cuda_fp16.h>
#include <cstdint>

#define NROWS 16384
#define DIN   512
#define DOUT  256

#define KC2 64
#define A2SZ (128 * 128)           // 16 KB  (fp16 SW128)
#define B2SZ (256 * 128)           // 32 KB
#define STG2 (A2SZ + B2SZ)         // 48 KB
#define SMEM2 (1024 + 4 * STG2)

// scratch (both in packed SW128 tile layout: [kt][256 n-rows x 64 halfs])
__device__ uint4 g_Wp4[DIN * DOUT / 8];    // W packed: 8 tiles
__device__ uint4 g_Hp4[NROWS * DOUT / 8];  // H packed: 256 tiles

// ---------------- helpers ----------------
__device__ __forceinline__ uint32_t smem_u32(const void* p) {
    uint32_t a;
    asm("{ .reg .u64 t; cvta.to.shared.u64 t, %1; cvt.u32.u64 %0, t; }"
        : "=r"(a) : "l"(p));
    return a;
}
__device__ __forceinline__ void sts64(uint32_t a, uint32_t x, uint32_t y) {
    asm volatile("st.shared.v2.b32 [%0], {%1, %2};" :: "r"(a), "r"(x), "r"(y) : "memory");
}
__device__ __forceinline__ uint32_t pack2(float x, float y) {
    __half2 h = __floats2half2_rn(x, y);
    return *reinterpret_cast<uint32_t*>(&h);
}
__device__ __forceinline__ void ldsm4(uint32_t* r, uint32_t addr) {
    asm volatile("ldmatrix.sync.aligned.m8n8.x4.shared.b16 {%0,%1,%2,%3}, [%4];"
                 : "=r"(r[0]), "=r"(r[1]), "=r"(r[2]), "=r"(r[3]) : "r"(addr));
}
__device__ __forceinline__ void mma16816(float* d, const uint32_t* a,
                                         uint32_t b0, uint32_t b1) {
    asm volatile(
        "mma.sync.aligned.m16n8k16.row.col.f32.f16.f16.f32 "
        "{%0,%1,%2,%3}, {%4,%5,%6,%7}, {%8,%9}, {%0,%1,%2,%3};"
        : "+f"(d[0]), "+f"(d[1]), "+f"(d[2]), "+f"(d[3])
        : "r"(a[0]), "r"(a[1]), "r"(a[2]), "r"(a[3]), "r"(b0), "r"(b1));
}
__device__ __forceinline__ void mbar_init(uint32_t addr, uint32_t count) {
    asm volatile("mbarrier.init.shared.b64 [%0], %1;" :: "r"(addr), "r"(count) : "memory");
}
__device__ __forceinline__ void mbar_expect_tx(uint32_t addr, uint32_t bytes) {
    asm volatile("mbarrier.arrive.expect_tx.shared.b64 _, [%0], %1;"
                 :: "r"(addr), "r"(bytes) : "memory");
}
__device__ __forceinline__ void mbar_arrive(uint32_t addr) {
    asm volatile("mbarrier.arrive.release.cta.shared.b64 _, [%0];" :: "r"(addr) : "memory");
}
__device__ __forceinline__ void mbar_wait(uint32_t addr, uint32_t parity) {
    asm volatile(
        "{\n\t.reg .pred P;\n\t"
        "W%=:\n\t"
        "mbarrier.try_wait.parity.acquire.cta.shared::cta.b64 P, [%0], %1, 0x989680;\n\t"
        "@!P bra W%=;\n\t"
        "}" :: "r"(addr), "r"(parity) : "memory");
}
__device__ __forceinline__ void bulk_g2s(uint32_t dst, const void* src,
                                         uint32_t bytes, uint32_t mbar) {
    asm volatile(
        "cp.async.bulk.shared::cta.global.mbarrier::complete_tx::bytes [%0], [%1], %2, [%3];"
        :: "r"(dst), "l"(src), "r"(bytes), "r"(mbar) : "memory");
}

// ---------------- W packing: W[k][n] f32 -> packed SW128 tiles ----------------
__global__ void pack_w_kernel(const float* __restrict__ W) {
    int idx = blockIdx.x * blockDim.x + threadIdx.x;
    if (idx >= DIN * DOUT) return;
    int k = idx / DOUT, n = idx % DOUT;
    int kt = k >> 6, kk = k & 63;
    int ch = kk >> 3, w = kk & 7;
    reinterpret_cast<__half*>(g_Wp4)[kt * 16384 + n * 64 + ((ch ^ (n & 7)) << 3) + w] =
        __float2half_rn(W[idx]);
}

// ---------------- fused GEMM: out = A(f32,[16384 x lda-strided]) @ Bpacked ----------------
// Warps 0-7: compute (64x64 tiles). Warps 8-11: convert A (32 rows each).
// full[s]: 128 convert lanes + 1 tx-arrive (B bulk) = 129.  empty[s]: 8 compute warps.
// EPI 0: out f32 row-major.  EPI 1: H packed tiles (+bias) -> g_Hp4.
template<int EPI>
__global__ void __launch_bounds__(384, 1)
gemm_fused(const float* __restrict__ A, long long lda,
           const uint4* __restrict__ Bp, int KT,
           float* __restrict__ out, const float* __restrict__ bias)
{
    extern __shared__ char sm[];
    const uint32_t sb = smem_u32(sm);
    const uint32_t mb = sb;
    const uint32_t tiles = sb + 1024;
    const int tid = threadIdx.x, lane = tid & 31, wid = tid >> 5;

    if (tid == 0) {
        #pragma unroll
        for (int s = 0; s < 4; s++) {
            mbar_init(mb + 8 * s, 129);      // full
            mbar_init(mb + 32 + 8 * s, 8);   // empty
        }
    }
    __syncthreads();

    if (wid >= 8) {
        // ---- convert-producer warps (A: fp32 gmem -> fp16 SW128 smem) ----
        const int w = wid - 8;
        const int lane4 = lane & 15, rh = lane >> 4;
        const int r0 = w * 32 + rh;
        const float* src0 = A + (size_t)(blockIdx.x * 128 + r0) * (size_t)lda + lane4 * 4;
        const uint32_t j16 = (uint32_t)(lane4 >> 1);
        const uint32_t low8 = (uint32_t)((lane4 & 1) * 8);

        for (int kt = 0; kt < KT; kt++) {
            int s = kt & 3, wrap = kt >> 2;
            if (kt >= 4) mbar_wait(mb + 32 + 8 * s, (wrap - 1) & 1);
            uint32_t stg = tiles + s * STG2;
            if (wid == 8 && lane == 0) {
                mbar_expect_tx(mb + 8 * s, B2SZ);
                bulk_g2s(stg + A2SZ, Bp + (size_t)kt * 2048, B2SZ, mb + 8 * s);
            }
            const float* srck = src0 + kt * KC2;
            #pragma unroll
            for (int it = 0; it < 16; it++) {
                int r = r0 + 2 * it;
                float4 v = *reinterpret_cast<const float4*>(srck + (size_t)(2 * it) * lda);
                uint32_t off = (uint32_t)(r * 128) + (((j16 ^ (uint32_t)(r & 7)) << 4) + low8);
                sts64(stg + off, pack2(v.x, v.y), pack2(v.z, v.w));
            }
            mbar_arrive(mb + 8 * s);   // per-lane release arrive
        }
        return;
    }

    // ---- compute warps (0..7), warp tile 64x64 ----
    const int warp_m = wid & 1, warp_n = wid >> 1;
    const int g = lane >> 2, c = lane & 3;

    float acc[4][8][4];
    #pragma unroll
    for (int mt = 0; mt < 4; mt++)
        #pragma unroll
        for (int nt = 0; nt < 8; nt++)
            #pragma unroll
            for (int e = 0; e < 4; e++) acc[mt][nt][e] = 0.f;

    const int arow = lane & 15, ahi = lane >> 4, s7 = lane & 7;
    const int brow = ((lane >> 4) << 3) + (lane & 7), bhi = (lane >> 3) & 1;
    uint32_t a_row_off[4], b_row_off[4];
    #pragma unroll
    for (int mt = 0; mt < 4; mt++)
        a_row_off[mt] = (uint32_t)((warp_m * 64 + mt * 16 + arow) * 128);
    #pragma unroll
    for (int ntp = 0; ntp < 4; ntp++)
        b_row_off[ntp] = (uint32_t)(A2SZ + (warp_n * 64 + ntp * 16 + brow) * 128);

    uint32_t afr[2][4][4], bfr[2][4][4];
    auto load_frags = [&](int buf, int k16, uint32_t stg) {
        uint32_t ja = (uint32_t)(((2 * k16 + ahi) ^ s7) << 4);
        #pragma unroll
        for (int mt = 0; mt < 4; mt++)
            ldsm4(afr[buf][mt], stg + a_row_off[mt] + ja);
        uint32_t jb = (uint32_t)(((2 * k16 + bhi) ^ s7) << 4);
        #pragma unroll
        for (int ntp = 0; ntp < 4; ntp++)
            ldsm4(bfr[buf][ntp], stg + b_row_off[ntp] + jb);
    };

    for (int kt = 0; kt < KT; kt++) {
        int s = kt & 3, ph = (kt >> 2) & 1;
        mbar_wait(mb + 8 * s, ph);
        uint32_t stg = tiles + s * STG2;
        load_frags(0, 0, stg);
        #pragma unroll
        for (int k16 = 0; k16 < 4; k16++) {
            int cur = k16 & 1;
            if (k16 < 3) load_frags(cur ^ 1, k16 + 1, stg);
            #pragma unroll
            for (int mt = 0; mt < 4; mt++)
                #pragma unroll
                for (int nt = 0; nt < 8; nt++)
                    mma16816(acc[mt][nt], afr[cur][mt],
                             bfr[cur][nt >> 1][(nt & 1) * 2],
                             bfr[cur][nt >> 1][(nt & 1) * 2 + 1]);
        }
        if (lane == 0) mbar_arrive(mb + 32 + 8 * s);   // stage consumed
    }

    if (EPI == 0) {
        int m0 = blockIdx.x * 128 + warp_m * 64;
        #pragma unroll
        for (int mt = 0; mt < 4; mt++) {
            #pragma unroll
            for (int nt = 0; nt < 8; nt++) {
                int r = m0 + mt * 16 + g;
                int n = warp_n * 64 + nt * 8 + c * 2;
                *reinterpret_cast<float2*>(out + (size_t)r * DOUT + n) =
                    make_float2(acc[mt][nt][0], acc[mt][nt][1]);
                *reinterpret_cast<float2*>(out + (size_t)(r + 8) * DOUT + n) =
                    make_float2(acc[mt][nt][2], acc[mt][nt][3]);
            }
        }
    } else {
        // stage 2 packed H tiles (64KB) in smem at offset 1024, then linear copy-out.
        asm volatile("bar.sync 1, 256;" ::: "memory");   // compute warps: stages free
        __half* smh = reinterpret_cast<__half*>(sm + 1024);
        #pragma unroll
        for (int mt = 0; mt < 4; mt++) {
            int r = warp_m * 64 + mt * 16 + g;           // local k row 0..127
            int t = r >> 6, kk = r & 63;
            int ch = kk >> 3, w = kk & 7;
            int tb = t * 16384;
            #pragma unroll
            for (int nt = 0; nt < 8; nt++) {
                int n = warp_n * 64 + nt * 8 + c * 2;
                float bn0 = bias[n], bn1 = bias[n + 1];
                int s0 = n & 7, s1 = (n + 1) & 7;
                smh[tb + n * 64       + ((ch ^ s0) << 3) + w] = __float2half_rn(acc[mt][nt][0] + bn0);
                smh[tb + (n + 1) * 64 + ((ch ^ s1) << 3) + w] = __float2half_rn(acc[mt][nt][1] + bn1);
                smh[tb + n * 64       + (((ch + 1) ^ s0) << 3) + w] = __float2half_rn(acc[mt][nt][2] + bn0);
                smh[tb + (n + 1) * 64 + (((ch + 1) ^ s1) << 3) + w] = __float2half_rn(acc[mt][nt][3] + bn1);
            }
        }
        asm volatile("bar.sync 1, 256;" ::: "memory");
        const uint4* sm4 = reinterpret_cast<const uint4*>(sm + 1024);
        uint4* gdst = g_Hp4 + (size_t)blockIdx.x * 4096;
        #pragma unroll
        for (int i = 0; i < 16; i++)
            gdst[tid + i * 256] = sm4[tid + i * 256];
    }
}

// ---------------- launch ----------------
extern "C" void kernel_launch(void* const* d_in, const int* in_sizes, int n_in,
                              void* d_out, int out_size) {
    const float* X = (const float*)d_in[0];
    const float* A = (const float*)d_in[1];
    const float* W = (const float*)d_in[2];
    const float* b = (const float*)d_in[3];
    float* out = (float*)d_out;

    cudaFuncSetAttribute(gemm_fused<0>, cudaFuncAttributeMaxDynamicSharedMemorySize, SMEM2);
    cudaFuncSetAttribute(gemm_fused<1>, cudaFuncAttributeMaxDynamicSharedMemorySize, SMEM2);

    void* wp = nullptr; void* hp = nullptr;
    cudaGetSymbolAddress(&wp, g_Wp4);
    cudaGetSymbolAddress(&hp, g_Hp4);

    pack_w_kernel<<<(DIN * DOUT + 255) / 256, 256>>>(W);
    // H = X @ W + b  (packed tiles)
    gemm_fused<1><<<128, 384, SMEM2>>>(X, DIN, (const uint4*)wp, DIN / KC2, nullptr, b);
    // Out = A_hat @ H
    gemm_fused<0><<<128, 384, SMEM2>>>(A, NROWS, (const uint4*)hp, NROWS / KC2, out, nullptr);
}